// round 10
// baseline (speedup 1.0000x reference)
#include <cuda_runtime.h>
#include <cuda_bf16.h>
#include <cuda_fp16.h>
#include <cstdint>

#define L       320
#define D       128
#define H       4
#define DH      32
#define NROW    (L*L)          // 102400
#define SCALE   0.17677669529663687f   // 1/sqrt(32)
#define LOG2E   1.4426950408889634f

// ---------------- scratch (static device memory, no allocation) ----------------
__device__ __nv_bfloat16 g_xh[NROW * D];   // layernormed pair, bf16 hi
__device__ __nv_bfloat16 g_xl[NROW * D];   // bf16 lo
__device__ float g_q   [NROW * D];   // [i][h][j][d]  (pre-scaled by SCALE*LOG2E)
__device__ float g_k   [NROW * D];
__device__ float g_v   [NROW * D];
__device__ float g_g   [NROW * D];   // row layout, sigmoid applied
__device__ uint32_t g_ohp[NROW * 64];  // gated attn out, bf16x2 hi (row layout)
__device__ uint32_t g_olp[NROW * 64];  // bf16x2 lo
__device__ float g_bias[L * H * L];  // [i][h][j]  (pre-scaled by LOG2E)
__device__ __nv_bfloat16 g_wh[5 * D * D];  // pre-split weights: Wq,Wk,Wv,Wg,Wo
__device__ __nv_bfloat16 g_wl[5 * D * D];

// single extern shared symbol for all kernels
extern __shared__ char smx[];

// ---------------- helpers ----------------
__device__ __forceinline__ float ex2f(float x) {
    float r; asm("ex2.approx.f32 %0, %1;" : "=f"(r) : "f"(x)); return r;
}
__device__ __forceinline__ uint32_t smem_u32(const void* p) {
    return (uint32_t)__cvta_generic_to_shared(p);
}
__device__ __forceinline__ void ldsm4(uint32_t* r, uint32_t addr) {
    asm volatile("ldmatrix.sync.aligned.m8n8.x4.shared.b16 {%0,%1,%2,%3}, [%4];"
                 : "=r"(r[0]), "=r"(r[1]), "=r"(r[2]), "=r"(r[3]) : "r"(addr));
}
__device__ __forceinline__ void mma16816(float* c, const uint32_t* a, const uint32_t* b) {
    asm volatile("mma.sync.aligned.m16n8k16.row.col.f32.bf16.bf16.f32 "
                 "{%0,%1,%2,%3}, {%4,%5,%6,%7}, {%8,%9}, {%0,%1,%2,%3};"
                 : "+f"(c[0]), "+f"(c[1]), "+f"(c[2]), "+f"(c[3])
                 : "r"(a[0]), "r"(a[1]), "r"(a[2]), "r"(a[3]), "r"(b[0]), "r"(b[1]));
}
__device__ __forceinline__ void mma16816h(float* c, const uint32_t* a, const uint32_t* b) {
    asm volatile("mma.sync.aligned.m16n8k16.row.col.f32.f16.f16.f32 "
                 "{%0,%1,%2,%3}, {%4,%5,%6,%7}, {%8,%9}, {%0,%1,%2,%3};"
                 : "+f"(c[0]), "+f"(c[1]), "+f"(c[2]), "+f"(c[3])
                 : "r"(a[0]), "r"(a[1]), "r"(a[2]), "r"(a[3]), "r"(b[0]), "r"(b[1]));
}
// split fp32 pair -> (hi bf16x2, lo bf16x2) packed as uint32
__device__ __forceinline__ void split2(float x0, float x1, uint32_t& hi, uint32_t& lo) {
    __nv_bfloat16 h0 = __float2bfloat16(x0);
    __nv_bfloat16 h1 = __float2bfloat16(x1);
    __nv_bfloat16 l0 = __float2bfloat16(x0 - __bfloat162float(h0));
    __nv_bfloat16 l1 = __float2bfloat16(x1 - __bfloat162float(h1));
    __nv_bfloat162 hp = {h0, h1}, lp = {l0, l1};
    hi = *(uint32_t*)&hp; lo = *(uint32_t*)&lp;
}
__device__ __forceinline__ uint32_t pkh2(float a, float b) {
    __half2 h = __floats2half2_rn(a, b);
    return *(uint32_t*)&h;
}

// shared tile geometry for GEMM kernels: 128 x 136 bf16 (272B stride)
#define TROW   272
#define TBYTES (128 * TROW)      // 34816
#define XH_OFF 0
#define XL_OFF TBYTES
#define WH_OFF (2 * TBYTES)
#define WL_OFF (3 * TBYTES)
#define GEMM_SMEM (4 * TBYTES)   // 139264

// ================= kernel 0: pre-split weights =================
__global__ void k_wsplit(const float* __restrict__ Wq, const float* __restrict__ Wk,
                         const float* __restrict__ Wv, const float* __restrict__ Wg,
                         const float* __restrict__ Wo) {
    int idx = blockIdx.x * blockDim.x + threadIdx.x;   // over 5*8192 float2
    if (idx >= 5 * 8192) return;
    int m = idx / 8192, off = idx % 8192;
    const float* W = (m == 0) ? Wq : (m == 1) ? Wk : (m == 2) ? Wv : (m == 3) ? Wg : Wo;
    float2 v = *(const float2*)&W[off * 2];
    uint32_t hi, lo;
    split2(v.x, v.y, hi, lo);
    *(uint32_t*)&g_wh[m * 16384 + off * 2] = hi;
    *(uint32_t*)&g_wl[m * 16384 + off * 2] = lo;
}

// ================= kernel 1: layernorm + bias projection =================
__global__ void k_ln_bias(const float* __restrict__ pair,
                          const float* __restrict__ nw,
                          const float* __restrict__ nb,
                          const float* __restrict__ Wb) {
    int row = blockIdx.x;
    int t   = threadIdx.x;
    int w   = t >> 5, lane = t & 31;

    float p = pair[(size_t)row * D + t];

    __shared__ float px[D];
    __shared__ float rs[4], rs2[4];
    px[t] = p;

    float s = p, s2 = p * p;
    #pragma unroll
    for (int o = 16; o > 0; o >>= 1) {
        s  += __shfl_xor_sync(0xffffffffu, s,  o);
        s2 += __shfl_xor_sync(0xffffffffu, s2, o);
    }
    if (lane == 0) { rs[w] = s; rs2[w] = s2; }
    __syncthreads();

    float mean = (rs[0] + rs[1] + rs[2] + rs[3]) * (1.0f / 128.0f);
    float var  = (rs2[0] + rs2[1] + rs2[2] + rs2[3]) * (1.0f / 128.0f) - mean * mean;
    float inv  = rsqrtf(var + 1e-5f);
    float xv = (p - mean) * inv * nw[t] + nb[t];
    __nv_bfloat16 xh = __float2bfloat16(xv);
    g_xh[(size_t)row * D + t] = xh;
    g_xl[(size_t)row * D + t] = __float2bfloat16(xv - __bfloat162float(xh));

    const float* wb = Wb + w * D;
    float bv = px[lane]      * wb[lane]
             + px[lane + 32] * wb[lane + 32]
             + px[lane + 64] * wb[lane + 64]
             + px[lane + 96] * wb[lane + 96];
    #pragma unroll
    for (int o = 16; o > 0; o >>= 1)
        bv += __shfl_xor_sync(0xffffffffu, bv, o);
    if (lane == 0) {
        int i = row / L, j = row % L;
        g_bias[(i * H + w) * L + j] = bv * LOG2E;
    }
}

// ---------- pure-copy staging: bf16 row-major [128x128] -> TROW-strided smem ----------
__device__ __forceinline__ void stage_copy(const __nv_bfloat16* __restrict__ src,
                                           char* sm, int off, int t, int nthr) {
    const uint4* s = (const uint4*)src;
    for (int idx = t; idx < 128 * 16; idx += nthr) {
        int r = idx >> 4, c = idx & 15;
        *(uint4*)(sm + off + r * TROW + c * 16) = s[r * 16 + c];
    }
}

// ---------- 3-term bf16-split GEMM, warp tile 32x32 ----------
__device__ __forceinline__ void gemm_tile32(uint32_t sb, float (&acc)[2][4][4],
                                            int lane, int wm, int wn) {
    int gq = lane >> 3, r8 = lane & 7;
    uint32_t a_off = (uint32_t)(wm * 32 + (gq & 1) * 8 + r8) * TROW + (uint32_t)(gq >> 1) * 16;
    uint32_t b_off = (uint32_t)(wn * 32 + (gq >> 1) * 8 + r8) * TROW + (uint32_t)(gq & 1) * 16;

    #pragma unroll
    for (int term = 0; term < 3; term++) {
        uint32_t abase = sb + ((term == 2) ? XL_OFF : XH_OFF) + a_off;
        uint32_t bbase = sb + ((term == 1) ? WL_OFF : WH_OFF) + b_off;
        #pragma unroll
        for (int ks = 0; ks < 8; ks++) {
            uint32_t kb = ks * 32;
            uint32_t a[2][4], b[2][4];
            ldsm4(a[0], abase + kb);
            ldsm4(a[1], abase + 16 * TROW + kb);
            ldsm4(b[0], bbase + kb);
            ldsm4(b[1], bbase + 16 * TROW + kb);
            #pragma unroll
            for (int mt = 0; mt < 2; mt++) {
                mma16816(acc[mt][0], a[mt], &b[0][0]);
                mma16816(acc[mt][1], a[mt], &b[0][2]);
                mma16816(acc[mt][2], a[mt], &b[1][0]);
                mma16816(acc[mt][3], a[mt], &b[1][2]);
            }
        }
    }
}

// ================= kernel 2: Q/K/V/G projections via mma.sync (512 thr) =================
__global__ __launch_bounds__(512) void k_proj(const float* __restrict__ bg) {
    char* sm = smx;
    uint32_t sb = smem_u32(sm);
    int t = threadIdx.x, w = t >> 5, lane = t & 31;
    int wm = w & 3, wn = w >> 2;          // 4x4 warp grid
    int base = blockIdx.x * 128;

    stage_copy(g_xh + (size_t)base * 128, sm, XH_OFF, t, 512);
    stage_copy(g_xl + (size_t)base * 128, sm, XL_OFF, t, 512);

    for (int m = 0; m < 4; m++) {
        __syncthreads();
        stage_copy(g_wh + m * 16384, sm, WH_OFF, t, 512);
        stage_copy(g_wl + m * 16384, sm, WL_OFF, t, 512);
        __syncthreads();

        float acc[2][4][4];
        #pragma unroll
        for (int mt = 0; mt < 2; mt++)
            #pragma unroll
            for (int nt = 0; nt < 4; nt++)
                #pragma unroll
                for (int k = 0; k < 4; k++) acc[mt][nt][k] = 0.0f;

        gemm_tile32(sb, acc, lane, wm, wn);

        #pragma unroll
        for (int mt = 0; mt < 2; mt++) {
            #pragma unroll
            for (int half = 0; half < 2; half++) {
                int R = base + wm * 32 + mt * 16 + (lane >> 2) + half * 8;
                int i = R / L, j = R % L;
                #pragma unroll
                for (int nt = 0; nt < 4; nt++) {
                    int d = nt * 8 + (lane & 3) * 2;
                    float v0 = acc[mt][nt][half * 2];
                    float v1 = acc[mt][nt][half * 2 + 1];
                    if (m < 3) {
                        float* dst = (m == 0) ? g_q : (m == 1) ? g_k : g_v;
                        float sc = (m == 0) ? (SCALE * LOG2E) : 1.0f;
                        *(float2*)&dst[(((size_t)i * H + wn) * L + j) * DH + d] =
                            make_float2(v0 * sc, v1 * sc);
                    } else {
                        int col = wn * 32 + d;
                        float a0 = v0 + bg[col], a1 = v1 + bg[col + 1];
                        *(float2*)&g_g[(size_t)R * D + col] =
                            make_float2(1.0f / (1.0f + __expf(-a0)),
                                        1.0f / (1.0f + __expf(-a1)));
                    }
                }
            }
        }
    }
}

// ================= kernel 3: tensor-core attention per (i,h) =================
// smem: Q hi fp16 [384 x 32] stride 80B; K hi/lo [320 x 32] stride 80B;
//       V^T hi/lo fp16 [32 x 320] stride 656B; bias [320] fp32
#define AQH 0
#define AKH 30720
#define AKL 56320
#define AVH 81920
#define AVL 102912
#define ABI 123904
#define ATTN_SMEM 125184

__global__ __launch_bounds__(256) void k_attn() {
    char* sm = smx;
    uint32_t sb = smem_u32(sm);

    int blk = blockIdx.x;
    int i = blk >> 2, h = blk & 3;
    int t = threadIdx.x, w = t >> 5, lane = t & 31;

    const float* Qg = g_q + ((size_t)i * H + h) * L * DH;
    const float* Kg = g_k + ((size_t)i * H + h) * L * DH;
    const float* Vg = g_v + ((size_t)i * H + h) * L * DH;

    for (int idx = t; idx < L * DH; idx += 256) {
        int j = idx >> 5, d = idx & 31;
        *(__half*)(sm + AQH + j * 80 + d * 2) = __float2half_rn(Qg[idx]);
        float kv = Kg[idx];
        __half kh = __float2half_rn(kv);
        *(__half*)(sm + AKH + j * 80 + d * 2) = kh;
        *(__half*)(sm + AKL + j * 80 + d * 2) = __float2half_rn(kv - __half2float(kh));
        float vv = Vg[idx];
        __half vh = __float2half_rn(vv);
        *(__half*)(sm + AVH + d * 656 + j * 2) = vh;
        *(__half*)(sm + AVL + d * 656 + j * 2) = __float2half_rn(vv - __half2float(vh));
    }
    // zero-pad Q rows 320..383
    for (int idx = t; idx < 64 * DH; idx += 256) {
        int j = 320 + (idx >> 5), d = idx & 31;
        *(__half*)(sm + AQH + j * 80 + d * 2) = __ushort_as_half(0);
    }
    for (int idx = t; idx < L; idx += 256)
        *(float*)(sm + ABI + idx * 4) = g_bias[(i * H + h) * L + idx];
    __syncthreads();

    if (w == 7) return;   // rows 336..383 are all padding

    int gq = lane >> 3, r8 = lane & 7;
    uint32_t qbase = sb + AQH + (uint32_t)(48 * w + (gq & 1) * 8 + r8) * 80 + (uint32_t)(gq >> 1) * 16;
    uint32_t kbase = sb + AKH + (uint32_t)((gq >> 1) * 8 + r8) * 80 + (uint32_t)(gq & 1) * 16;
    uint32_t vbase = sb + AVH + (uint32_t)((gq >> 1) * 8 + r8) * 656 + (uint32_t)(gq & 1) * 16;
    const float* Bsp = (const float*)(sm + ABI);

    float O[3][4][4];
    float ds[3][2];
    #pragma unroll
    for (int mt = 0; mt < 3; mt++) {
        ds[mt][0] = 0.0f; ds[mt][1] = 0.0f;
        #pragma unroll
        for (int nt = 0; nt < 4; nt++)
            #pragma unroll
            for (int k = 0; k < 4; k++) O[mt][nt][k] = 0.0f;
    }

    #pragma unroll 1
    for (int nb = 0; nb < 5; nb++) {
        // ---- S = Q K^T (2-term fp16 split: Qh*Kh + Qh*Kl) ----
        float S[3][8][4];
        #pragma unroll
        for (int mt = 0; mt < 3; mt++)
            #pragma unroll
            for (int nt = 0; nt < 8; nt++)
                #pragma unroll
                for (int k = 0; k < 4; k++) S[mt][nt][k] = 0.0f;

        #pragma unroll
        for (int ks = 0; ks < 2; ks++) {
            uint32_t Ah[3][4], Bh[4][4], Bl[4][4];
            #pragma unroll
            for (int mt = 0; mt < 3; mt++)
                ldsm4(Ah[mt], qbase + mt * 1280 + ks * 32);
            #pragma unroll
            for (int nt = 0; nt < 4; nt++) {
                uint32_t ko = (uint32_t)(nb * 64 + nt * 16) * 80 + ks * 32;
                ldsm4(Bh[nt], kbase + ko);
                ldsm4(Bl[nt], kbase + (AKL - AKH) + ko);
            }
            #pragma unroll
            for (int mt = 0; mt < 3; mt++)
                #pragma unroll
                for (int nt = 0; nt < 4; nt++) {
                    mma16816h(S[mt][2 * nt],     Ah[mt], &Bh[nt][0]);
                    mma16816h(S[mt][2 * nt + 1], Ah[mt], &Bh[nt][2]);
                    mma16816h(S[mt][2 * nt],     Ah[mt], &Bl[nt][0]);
                    mma16816h(S[mt][2 * nt + 1], Ah[mt], &Bl[nt][2]);
                }
        }

        // ---- bias + exp2 + repack (hi only) + PV (Ph*Vh + Ph*Vl) ----
        #pragma unroll
        for (int nt = 0; nt < 4; nt++) {
            int c0 = nb * 64 + nt * 16 + 2 * (lane & 3);
            float b00 = Bsp[c0], b01 = Bsp[c0 + 1];
            float b10 = Bsp[c0 + 8], b11 = Bsp[c0 + 9];

            uint32_t PAh[3][4];
            #pragma unroll
            for (int mt = 0; mt < 3; mt++) {
                float e00 = ex2f(S[mt][2 * nt][0] + b00);
                float e01 = ex2f(S[mt][2 * nt][1] + b01);
                float e10 = ex2f(S[mt][2 * nt][2] + b00);
                float e11 = ex2f(S[mt][2 * nt][3] + b01);
                float f00 = ex2f(S[mt][2 * nt + 1][0] + b10);
                float f01 = ex2f(S[mt][2 * nt + 1][1] + b11);
                float f10 = ex2f(S[mt][2 * nt + 1][2] + b10);
                float f11 = ex2f(S[mt][2 * nt + 1][3] + b11);
                ds[mt][0] += (e00 + e01) + (f00 + f01);
                ds[mt][1] += (e10 + e11) + (f10 + f11);
                PAh[mt][0] = pkh2(e00, e01);
                PAh[mt][1] = pkh2(e10, e11);
                PAh[mt][2] = pkh2(f00, f01);
                PAh[mt][3] = pkh2(f10, f11);
            }

            uint32_t Vh2[2][4], Vl2[2][4];
            #pragma unroll
            for (int dn = 0; dn < 2; dn++) {
                uint32_t vo = (uint32_t)dn * (16 * 656) + (uint32_t)(nb * 64 + nt * 16) * 2;
                ldsm4(Vh2[dn], vbase + vo);
                ldsm4(Vl2[dn], vbase + (AVL - AVH) + vo);
            }
            #pragma unroll
            for (int mt = 0; mt < 3; mt++)
                #pragma unroll
                for (int dn = 0; dn < 2; dn++) {
                    mma16816h(O[mt][2 * dn],     PAh[mt], &Vh2[dn][0]);
                    mma16816h(O[mt][2 * dn + 1], PAh[mt], &Vh2[dn][2]);
                    mma16816h(O[mt][2 * dn],     PAh[mt], &Vl2[dn][0]);
                    mma16816h(O[mt][2 * dn + 1], PAh[mt], &Vl2[dn][2]);
                }
        }
    }

    // reduce row-sums across the 4 lanes sharing each row
    #pragma unroll
    for (int mt = 0; mt < 3; mt++)
        #pragma unroll
        for (int rr = 0; rr < 2; rr++) {
            ds[mt][rr] += __shfl_xor_sync(0xffffffffu, ds[mt][rr], 1);
            ds[mt][rr] += __shfl_xor_sync(0xffffffffu, ds[mt][rr], 2);
        }

    // normalize, gate, split to bf16 hi/lo, store
    #pragma unroll
    for (int mt = 0; mt < 3; mt++) {
        float inv0 = __fdividef(1.0f, ds[mt][0]);
        float inv1 = __fdividef(1.0f, ds[mt][1]);
        #pragma unroll
        for (int half = 0; half < 2; half++) {
            int r = 48 * w + mt * 16 + (lane >> 2) + half * 8;
            if (r < L) {
                float inv = half ? inv1 : inv0;
                size_t R = ((size_t)i * L + r) * D + h * DH;
                #pragma unroll
                for (int nt = 0; nt < 4; nt++) {
                    int d = nt * 8 + 2 * (lane & 3);
                    float2 gv = *(const float2*)&g_g[R + d];
                    float o0 = O[mt][nt][half * 2] * inv * gv.x;
                    float o1 = O[mt][nt][half * 2 + 1] * inv * gv.y;
                    uint32_t hi, lo;
                    split2(o0, o1, hi, lo);
                    g_ohp[(R + d) >> 1] = hi;
                    g_olp[(R + d) >> 1] = lo;
                }
            }
        }
    }
}

// ================= kernel 4: output projection + residual (512 thr) =================
__global__ __launch_bounds__(512) void k_out(const float* __restrict__ bo,
                                             const float* __restrict__ pair,
                                             float* __restrict__ out) {
    char* sm = smx;
    uint32_t sb = smem_u32(sm);
    int t = threadIdx.x, w = t >> 5, lane = t & 31;
    int wm = w & 3, wn = w >> 2;
    int base = blockIdx.x * 128;

    stage_copy((const __nv_bfloat16*)g_ohp + (size_t)base * 128, sm, XH_OFF, t, 512);
    stage_copy((const __nv_bfloat16*)g_olp + (size_t)base * 128, sm, XL_OFF, t, 512);
    stage_copy(g_wh + 4 * 16384, sm, WH_OFF, t, 512);
    stage_copy(g_wl + 4 * 16384, sm, WL_OFF, t, 512);
    __syncthreads();

    float acc[2][4][4];
    #pragma unroll
    for (int mt = 0; mt < 2; mt++)
        #pragma unroll
        for (int nt = 0; nt < 4; nt++)
            #pragma unroll
            for (int k = 0; k < 4; k++) acc[mt][nt][k] = 0.0f;

    gemm_tile32(sb, acc, lane, wm, wn);

    #pragma unroll
    for (int mt = 0; mt < 2; mt++) {
        #pragma unroll
        for (int half = 0; half < 2; half++) {
            size_t R = (size_t)base + wm * 32 + mt * 16 + (lane >> 2) + half * 8;
            #pragma unroll
            for (int nt = 0; nt < 4; nt++) {
                int col = wn * 32 + nt * 8 + (lane & 3) * 2;
                float2 bov = *(const float2*)&bo[col];
                float2 pv = *(const float2*)&pair[R * D + col];
                *(float2*)&out[R * D + col] =
                    make_float2(pv.x + acc[mt][nt][half * 2]     + bov.x,
                                pv.y + acc[mt][nt][half * 2 + 1] + bov.y);
            }
        }
    }
}

// ================= launch =================
extern "C" void kernel_launch(void* const* d_in, const int* in_sizes, int n_in,
                              void* d_out, int out_size) {
    const float* pair  = (const float*)d_in[0];
    const float* nw    = (const float*)d_in[1];
    const float* nb    = (const float*)d_in[2];
    const float* Wq    = (const float*)d_in[3];
    const float* Wk    = (const float*)d_in[4];
    const float* Wv    = (const float*)d_in[5];
    const float* Wg    = (const float*)d_in[6];
    const float* bg    = (const float*)d_in[7];
    const float* Wo    = (const float*)d_in[8];
    const float* bo    = (const float*)d_in[9];
    const float* Wb    = (const float*)d_in[10];
    float* out = (float*)d_out;

    static bool attr_set = false;
    if (!attr_set) {
        cudaFuncSetAttribute(k_attn, cudaFuncAttributeMaxDynamicSharedMemorySize, ATTN_SMEM);
        cudaFuncSetAttribute(k_proj, cudaFuncAttributeMaxDynamicSharedMemorySize, GEMM_SMEM);
        cudaFuncSetAttribute(k_out,  cudaFuncAttributeMaxDynamicSharedMemorySize, GEMM_SMEM);
        attr_set = true;
    }

    k_wsplit <<<(5 * 8192 + 255) / 256, 256>>>(Wq, Wk, Wv, Wg, Wo);
    k_ln_bias<<<NROW, 128>>>(pair, nw, nb, Wb);
    k_proj   <<<NROW / 128, 512, GEMM_SMEM>>>(bg);
    k_attn   <<<L * H, 256, ATTN_SMEM>>>();
    k_out    <<<NROW / 128, 512, GEMM_SMEM>>>(bo, pair, out);
}

// round 11
// speedup vs baseline: 1.6619x; 1.6619x over previous
#include <cuda_runtime.h>
#include <cuda_bf16.h>
#include <cuda_fp16.h>
#include <cstdint>

#define L       320
#define D       128
#define H       4
#define DH      32
#define NROW    (L*L)          // 102400
#define SCALE   0.17677669529663687f   // 1/sqrt(32)
#define LOG2E   1.4426950408889634f

// ---------------- scratch (static device memory, no allocation) ----------------
__device__ float g_x   [NROW * D];   // layernormed pair
__device__ float g_q   [NROW * D];   // [i][h][j][d]  (pre-scaled by SCALE*LOG2E)
__device__ float g_k   [NROW * D];
__device__ float g_v   [NROW * D];
__device__ float g_g   [NROW * D];   // row layout, sigmoid applied
__device__ float g_o   [NROW * D];   // gated attention output, row layout
__device__ float g_bias[L * H * L];  // [i][h][j]  (pre-scaled by LOG2E)

// single extern shared symbol for all kernels
extern __shared__ char smx[];

// ---------------- helpers ----------------
__device__ __forceinline__ float ex2f(float x) {
    float r; asm("ex2.approx.f32 %0, %1;" : "=f"(r) : "f"(x)); return r;
}
__device__ __forceinline__ uint32_t smem_u32(const void* p) {
    return (uint32_t)__cvta_generic_to_shared(p);
}
__device__ __forceinline__ void ldsm4(uint32_t* r, uint32_t addr) {
    asm volatile("ldmatrix.sync.aligned.m8n8.x4.shared.b16 {%0,%1,%2,%3}, [%4];"
                 : "=r"(r[0]), "=r"(r[1]), "=r"(r[2]), "=r"(r[3]) : "r"(addr));
}
__device__ __forceinline__ void mma16816(float* c, const uint32_t* a, const uint32_t* b) {
    asm volatile("mma.sync.aligned.m16n8k16.row.col.f32.bf16.bf16.f32 "
                 "{%0,%1,%2,%3}, {%4,%5,%6,%7}, {%8,%9}, {%0,%1,%2,%3};"
                 : "+f"(c[0]), "+f"(c[1]), "+f"(c[2]), "+f"(c[3])
                 : "r"(a[0]), "r"(a[1]), "r"(a[2]), "r"(a[3]), "r"(b[0]), "r"(b[1]));
}
__device__ __forceinline__ void mma16816h(float* c, const uint32_t* a, const uint32_t* b) {
    asm volatile("mma.sync.aligned.m16n8k16.row.col.f32.f16.f16.f32 "
                 "{%0,%1,%2,%3}, {%4,%5,%6,%7}, {%8,%9}, {%0,%1,%2,%3};"
                 : "+f"(c[0]), "+f"(c[1]), "+f"(c[2]), "+f"(c[3])
                 : "r"(a[0]), "r"(a[1]), "r"(a[2]), "r"(a[3]), "r"(b[0]), "r"(b[1]));
}
// split fp32 pair -> (hi bf16x2, lo bf16x2) packed as uint32
__device__ __forceinline__ void split2(float x0, float x1, uint32_t& hi, uint32_t& lo) {
    __nv_bfloat16 h0 = __float2bfloat16(x0);
    __nv_bfloat16 h1 = __float2bfloat16(x1);
    __nv_bfloat16 l0 = __float2bfloat16(x0 - __bfloat162float(h0));
    __nv_bfloat16 l1 = __float2bfloat16(x1 - __bfloat162float(h1));
    __nv_bfloat162 hp = {h0, h1}, lp = {l0, l1};
    hi = *(uint32_t*)&hp; lo = *(uint32_t*)&lp;
}
__device__ __forceinline__ uint32_t pkh2(float a, float b) {
    __half2 h = __floats2half2_rn(a, b);
    return *(uint32_t*)&h;
}

// shared tile geometry for GEMM kernels: 128 x 136 bf16 (272B stride)
#define TROW   272
#define TBYTES (128 * TROW)      // 34816
#define XH_OFF 0
#define XL_OFF TBYTES
#define WH_OFF (2 * TBYTES)
#define WL_OFF (3 * TBYTES)
#define GEMM_SMEM (4 * TBYTES)   // 139264

// ================= kernel 1: layernorm + bias projection =================
__global__ void k_ln_bias(const float* __restrict__ pair,
                          const float* __restrict__ nw,
                          const float* __restrict__ nb,
                          const float* __restrict__ Wb) {
    int row = blockIdx.x;
    int t   = threadIdx.x;
    int w   = t >> 5, lane = t & 31;

    float p = pair[(size_t)row * D + t];

    __shared__ float px[D];
    __shared__ float rs[4], rs2[4];
    px[t] = p;

    float s = p, s2 = p * p;
    #pragma unroll
    for (int o = 16; o > 0; o >>= 1) {
        s  += __shfl_xor_sync(0xffffffffu, s,  o);
        s2 += __shfl_xor_sync(0xffffffffu, s2, o);
    }
    if (lane == 0) { rs[w] = s; rs2[w] = s2; }
    __syncthreads();

    float mean = (rs[0] + rs[1] + rs[2] + rs[3]) * (1.0f / 128.0f);
    float var  = (rs2[0] + rs2[1] + rs2[2] + rs2[3]) * (1.0f / 128.0f) - mean * mean;
    float inv  = rsqrtf(var + 1e-5f);
    g_x[(size_t)row * D + t] = (p - mean) * inv * nw[t] + nb[t];

    const float* wb = Wb + w * D;
    float bv = px[lane]      * wb[lane]
             + px[lane + 32] * wb[lane + 32]
             + px[lane + 64] * wb[lane + 64]
             + px[lane + 96] * wb[lane + 96];
    #pragma unroll
    for (int o = 16; o > 0; o >>= 1)
        bv += __shfl_xor_sync(0xffffffffu, bv, o);
    if (lane == 0) {
        int i = row / L, j = row % L;
        g_bias[(i * H + w) * L + j] = bv * LOG2E;
    }
}

// ---------- shared staging: fp32 [rows x 128] -> bf16 hi/lo tiles ----------
__device__ __forceinline__ void stage_tile(const float* __restrict__ src, char* sm,
                                           int hi_off, int lo_off, int t) {
    for (int idx = t; idx < 128 * 64; idx += 256) {
        int r = idx >> 6, cp = idx & 63;
        float2 v = *(const float2*)&src[(size_t)r * 128 + cp * 2];
        uint32_t hi, lo;
        split2(v.x, v.y, hi, lo);
        *(uint32_t*)(sm + hi_off + r * TROW + cp * 4) = hi;
        *(uint32_t*)(sm + lo_off + r * TROW + cp * 4) = lo;
    }
}

// ---------- 3-term bf16-split 128x128x128 GEMM into registers (64x32 warp tile) ----------
__device__ __forceinline__ void gemm_tile(uint32_t sb, float (&acc)[4][4][4],
                                          int lane, int wm, int wn) {
    int gq = lane >> 3, r8 = lane & 7;
    uint32_t a_off = (uint32_t)(wm * 64 + (gq & 1) * 8 + r8) * TROW + (uint32_t)(gq >> 1) * 16;
    uint32_t b_off = (uint32_t)(wn * 32 + (gq >> 1) * 8 + r8) * TROW + (uint32_t)(gq & 1) * 16;

    #pragma unroll
    for (int term = 0; term < 3; term++) {
        uint32_t abase = sb + ((term == 2) ? XL_OFF : XH_OFF) + a_off;
        uint32_t bbase = sb + ((term == 1) ? WL_OFF : WH_OFF) + b_off;
        #pragma unroll
        for (int ks = 0; ks < 8; ks++) {
            uint32_t kb = ks * 32;
            uint32_t a[4][4], b[2][4];
            #pragma unroll
            for (int mt = 0; mt < 4; mt++)
                ldsm4(a[mt], abase + mt * (16 * TROW) + kb);
            #pragma unroll
            for (int nb = 0; nb < 2; nb++)
                ldsm4(b[nb], bbase + nb * (16 * TROW) + kb);
            #pragma unroll
            for (int mt = 0; mt < 4; mt++) {
                mma16816(acc[mt][0], a[mt], &b[0][0]);
                mma16816(acc[mt][1], a[mt], &b[0][2]);
                mma16816(acc[mt][2], a[mt], &b[1][0]);
                mma16816(acc[mt][3], a[mt], &b[1][2]);
            }
        }
    }
}

// ================= kernel 2: Q/K/V/G projections via mma.sync =================
__global__ __launch_bounds__(256) void k_proj(const float* __restrict__ Wq,
                                              const float* __restrict__ Wk,
                                              const float* __restrict__ Wv,
                                              const float* __restrict__ Wg,
                                              const float* __restrict__ bg) {
    char* sm = smx;
    uint32_t sb = smem_u32(sm);
    int t = threadIdx.x, w = t >> 5, lane = t & 31;
    int wm = w & 1, wn = w >> 1;
    int base = blockIdx.x * 128;

    stage_tile(g_x + (size_t)base * 128, sm, XH_OFF, XL_OFF, t);

    for (int m = 0; m < 4; m++) {
        const float* W = (m == 0) ? Wq : (m == 1) ? Wk : (m == 2) ? Wv : Wg;
        __syncthreads();
        stage_tile(W, sm, WH_OFF, WL_OFF, t);
        __syncthreads();

        float acc[4][4][4];
        #pragma unroll
        for (int mt = 0; mt < 4; mt++)
            #pragma unroll
            for (int nt = 0; nt < 4; nt++)
                #pragma unroll
                for (int k = 0; k < 4; k++) acc[mt][nt][k] = 0.0f;

        gemm_tile(sb, acc, lane, wm, wn);

        #pragma unroll
        for (int mt = 0; mt < 4; mt++) {
            #pragma unroll
            for (int nt = 0; nt < 4; nt++) {
                int col = wn * 32 + nt * 8 + (lane & 3) * 2;
                #pragma unroll
                for (int half = 0; half < 2; half++) {
                    int R = base + wm * 64 + mt * 16 + (lane >> 2) + half * 8;
                    float v0 = acc[mt][nt][half * 2];
                    float v1 = acc[mt][nt][half * 2 + 1];
                    int i = R / L, j = R % L;
                    if (m < 3) {
                        float* dst = (m == 0) ? g_q : (m == 1) ? g_k : g_v;
                        float sc = (m == 0) ? (SCALE * LOG2E) : 1.0f;
                        int h = col >> 5, d = col & 31;
                        *(float2*)&dst[(((size_t)i * H + h) * L + j) * DH + d] =
                            make_float2(v0 * sc, v1 * sc);
                    } else {
                        float a0 = v0 + bg[col], a1 = v1 + bg[col + 1];
                        *(float2*)&g_g[(size_t)R * D + col] =
                            make_float2(1.0f / (1.0f + __expf(-a0)),
                                        1.0f / (1.0f + __expf(-a1)));
                    }
                }
            }
        }
    }
}

// ================= kernel 3: tensor-core attention per (i,h), 2 CTAs/SM =================
// smem: Q hi fp16 [384 x 32] stride 80B; K hi/lo [320 x 32] stride 80B;
//       V^T hi fp16 [32 x 320] stride 656B; bias [320] fp32
#define AQH 0
#define AKH 30720
#define AKL 56320
#define AVH 81920
#define ABI 102912
#define ATTN_SMEM 104192

__global__ __launch_bounds__(256, 2) void k_attn() {
    char* sm = smx;
    uint32_t sb = smem_u32(sm);

    int blk = blockIdx.x;
    int i = blk >> 2, h = blk & 3;
    int t = threadIdx.x, w = t >> 5, lane = t & 31;

    const float* Qg = g_q + ((size_t)i * H + h) * L * DH;
    const float* Kg = g_k + ((size_t)i * H + h) * L * DH;
    const float* Vg = g_v + ((size_t)i * H + h) * L * DH;

    for (int idx = t; idx < L * DH; idx += 256) {
        int j = idx >> 5, d = idx & 31;
        *(__half*)(sm + AQH + j * 80 + d * 2) = __float2half_rn(Qg[idx]);
        float kv = Kg[idx];
        __half kh = __float2half_rn(kv);
        *(__half*)(sm + AKH + j * 80 + d * 2) = kh;
        *(__half*)(sm + AKL + j * 80 + d * 2) = __float2half_rn(kv - __half2float(kh));
        *(__half*)(sm + AVH + d * 656 + j * 2) = __float2half_rn(Vg[idx]);
    }
    // zero-pad Q rows 320..383
    for (int idx = t; idx < 64 * DH; idx += 256) {
        int j = 320 + (idx >> 5), d = idx & 31;
        *(__half*)(sm + AQH + j * 80 + d * 2) = __ushort_as_half(0);
    }
    for (int idx = t; idx < L; idx += 256)
        *(float*)(sm + ABI + idx * 4) = g_bias[(i * H + h) * L + idx];
    __syncthreads();

    if (w == 7) return;   // rows 336..383 are all padding

    int gq = lane >> 3, r8 = lane & 7;
    uint32_t qbase = sb + AQH + (uint32_t)(48 * w + (gq & 1) * 8 + r8) * 80 + (uint32_t)(gq >> 1) * 16;
    uint32_t kbase = sb + AKH + (uint32_t)((gq >> 1) * 8 + r8) * 80 + (uint32_t)(gq & 1) * 16;
    uint32_t vbase = sb + AVH + (uint32_t)((gq >> 1) * 8 + r8) * 656 + (uint32_t)(gq & 1) * 16;
    const float* Bsp = (const float*)(sm + ABI);

    float O[3][4][4];
    float ds[3][2];
    #pragma unroll
    for (int mt = 0; mt < 3; mt++) {
        ds[mt][0] = 0.0f; ds[mt][1] = 0.0f;
        #pragma unroll
        for (int nt = 0; nt < 4; nt++)
            #pragma unroll
            for (int k = 0; k < 4; k++) O[mt][nt][k] = 0.0f;
    }

    #pragma unroll 1
    for (int nb = 0; nb < 10; nb++) {   // 32 keys per chunk
        // ---- S = Q K^T (2-term fp16 split: Qh*Kh + Qh*Kl) ----
        float S[3][4][4];
        #pragma unroll
        for (int mt = 0; mt < 3; mt++)
            #pragma unroll
            for (int nt = 0; nt < 4; nt++)
                #pragma unroll
                for (int k = 0; k < 4; k++) S[mt][nt][k] = 0.0f;

        #pragma unroll
        for (int ks = 0; ks < 2; ks++) {
            uint32_t Ah[3][4], Bh[2][4], Bl[2][4];
            #pragma unroll
            for (int mt = 0; mt < 3; mt++)
                ldsm4(Ah[mt], qbase + mt * 1280 + ks * 32);
            #pragma unroll
            for (int nt = 0; nt < 2; nt++) {
                uint32_t ko = (uint32_t)(nb * 32 + nt * 16) * 80 + ks * 32;
                ldsm4(Bh[nt], kbase + ko);
                ldsm4(Bl[nt], kbase + (AKL - AKH) + ko);
            }
            #pragma unroll
            for (int mt = 0; mt < 3; mt++)
                #pragma unroll
                for (int nt = 0; nt < 2; nt++) {
                    mma16816h(S[mt][2 * nt],     Ah[mt], &Bh[nt][0]);
                    mma16816h(S[mt][2 * nt + 1], Ah[mt], &Bh[nt][2]);
                    mma16816h(S[mt][2 * nt],     Ah[mt], &Bl[nt][0]);
                    mma16816h(S[mt][2 * nt + 1], Ah[mt], &Bl[nt][2]);
                }
        }

        // ---- bias + exp2 + repack (hi only) + PV (hi only) ----
        #pragma unroll
        for (int nt = 0; nt < 2; nt++) {
            int c0 = nb * 32 + nt * 16 + 2 * (lane & 3);
            float b00 = Bsp[c0], b01 = Bsp[c0 + 1];
            float b10 = Bsp[c0 + 8], b11 = Bsp[c0 + 9];

            uint32_t PAh[3][4];
            #pragma unroll
            for (int mt = 0; mt < 3; mt++) {
                float e00 = ex2f(S[mt][2 * nt][0] + b00);
                float e01 = ex2f(S[mt][2 * nt][1] + b01);
                float e10 = ex2f(S[mt][2 * nt][2] + b00);
                float e11 = ex2f(S[mt][2 * nt][3] + b01);
                float f00 = ex2f(S[mt][2 * nt + 1][0] + b10);
                float f01 = ex2f(S[mt][2 * nt + 1][1] + b11);
                float f10 = ex2f(S[mt][2 * nt + 1][2] + b10);
                float f11 = ex2f(S[mt][2 * nt + 1][3] + b11);
                ds[mt][0] += (e00 + e01) + (f00 + f01);
                ds[mt][1] += (e10 + e11) + (f10 + f11);
                PAh[mt][0] = pkh2(e00, e01);
                PAh[mt][1] = pkh2(e10, e11);
                PAh[mt][2] = pkh2(f00, f01);
                PAh[mt][3] = pkh2(f10, f11);
            }

            uint32_t Vh2[2][4];
            #pragma unroll
            for (int dn = 0; dn < 2; dn++) {
                uint32_t vo = (uint32_t)dn * (16 * 656) + (uint32_t)(nb * 32 + nt * 16) * 2;
                ldsm4(Vh2[dn], vbase + vo);
            }
            #pragma unroll
            for (int mt = 0; mt < 3; mt++)
                #pragma unroll
                for (int dn = 0; dn < 2; dn++) {
                    mma16816h(O[mt][2 * dn],     PAh[mt], &Vh2[dn][0]);
                    mma16816h(O[mt][2 * dn + 1], PAh[mt], &Vh2[dn][2]);
                }
        }
    }

    // reduce row-sums across the 4 lanes sharing each row
    #pragma unroll
    for (int mt = 0; mt < 3; mt++)
        #pragma unroll
        for (int rr = 0; rr < 2; rr++) {
            ds[mt][rr] += __shfl_xor_sync(0xffffffffu, ds[mt][rr], 1);
            ds[mt][rr] += __shfl_xor_sync(0xffffffffu, ds[mt][rr], 2);
        }

    // normalize, gate, store
    #pragma unroll
    for (int mt = 0; mt < 3; mt++) {
        float inv0 = __fdividef(1.0f, ds[mt][0]);
        float inv1 = __fdividef(1.0f, ds[mt][1]);
        #pragma unroll
        for (int half = 0; half < 2; half++) {
            int r = 48 * w + mt * 16 + (lane >> 2) + half * 8;
            if (r < L) {
                float inv = half ? inv1 : inv0;
                size_t R = ((size_t)i * L + r) * D + h * DH;
                #pragma unroll
                for (int nt = 0; nt < 4; nt++) {
                    int d = nt * 8 + 2 * (lane & 3);
                    float2 gv = *(const float2*)&g_g[R + d];
                    *(float2*)&g_o[R + d] =
                        make_float2(O[mt][nt][half * 2] * inv * gv.x,
                                    O[mt][nt][half * 2 + 1] * inv * gv.y);
                }
            }
        }
    }
}

// ================= kernel 4: output projection + residual via mma.sync =================
__global__ __launch_bounds__(256) void k_out(const float* __restrict__ Wo,
                                             const float* __restrict__ bo,
                                             const float* __restrict__ pair,
                                             float* __restrict__ out) {
    char* sm = smx;
    uint32_t sb = smem_u32(sm);
    int t = threadIdx.x, w = t >> 5, lane = t & 31;
    int wm = w & 1, wn = w >> 1;
    int base = blockIdx.x * 128;

    stage_tile(g_o + (size_t)base * 128, sm, XH_OFF, XL_OFF, t);
    stage_tile(Wo, sm, WH_OFF, WL_OFF, t);
    __syncthreads();

    float acc[4][4][4];
    #pragma unroll
    for (int mt = 0; mt < 4; mt++)
        #pragma unroll
        for (int nt = 0; nt < 4; nt++)
            #pragma unroll
            for (int k = 0; k < 4; k++) acc[mt][nt][k] = 0.0f;

    gemm_tile(sb, acc, lane, wm, wn);

    #pragma unroll
    for (int mt = 0; mt < 4; mt++) {
        #pragma unroll
        for (int nt = 0; nt < 4; nt++) {
            int col = wn * 32 + nt * 8 + (lane & 3) * 2;
            float2 bov = *(const float2*)&bo[col];
            #pragma unroll
            for (int half = 0; half < 2; half++) {
                size_t R = (size_t)base + wm * 64 + mt * 16 + (lane >> 2) + half * 8;
                float2 pv = *(const float2*)&pair[R * D + col];
                *(float2*)&out[R * D + col] =
                    make_float2(pv.x + acc[mt][nt][half * 2]     + bov.x,
                                pv.y + acc[mt][nt][half * 2 + 1] + bov.y);
            }
        }
    }
}

// ================= launch =================
extern "C" void kernel_launch(void* const* d_in, const int* in_sizes, int n_in,
                              void* d_out, int out_size) {
    const float* pair  = (const float*)d_in[0];
    const float* nw    = (const float*)d_in[1];
    const float* nb    = (const float*)d_in[2];
    const float* Wq    = (const float*)d_in[3];
    const float* Wk    = (const float*)d_in[4];
    const float* Wv    = (const float*)d_in[5];
    const float* Wg    = (const float*)d_in[6];
    const float* bg    = (const float*)d_in[7];
    const float* Wo    = (const float*)d_in[8];
    const float* bo    = (const float*)d_in[9];
    const float* Wb    = (const float*)d_in[10];
    float* out = (float*)d_out;

    static bool attr_set = false;
    if (!attr_set) {
        cudaFuncSetAttribute(k_attn, cudaFuncAttributeMaxDynamicSharedMemorySize, ATTN_SMEM);
        cudaFuncSetAttribute(k_proj, cudaFuncAttributeMaxDynamicSharedMemorySize, GEMM_SMEM);
        cudaFuncSetAttribute(k_out,  cudaFuncAttributeMaxDynamicSharedMemorySize, GEMM_SMEM);
        attr_set = true;
    }

    k_ln_bias<<<NROW, 128>>>(pair, nw, nb, Wb);
    k_proj   <<<NROW / 128, 256, GEMM_SMEM>>>(Wq, Wk, Wv, Wg, bg);
    k_attn   <<<L * H, 256, ATTN_SMEM>>>();
    k_out    <<<NROW / 128, 256, GEMM_SMEM>>>(Wo, bo, pair, out);
}

// round 12
// speedup vs baseline: 1.6663x; 1.0027x over previous
#include <cuda_runtime.h>
#include <cuda_bf16.h>
#include <cuda_fp16.h>
#include <cstdint>

#define L       320
#define D       128
#define H       4
#define DH      32
#define NROW    (L*L)          // 102400
#define SCALE   0.17677669529663687f   // 1/sqrt(32)
#define LOG2E   1.4426950408889634f

// ---------------- scratch (static device memory, no allocation) ----------------
__device__ __align__(16) __nv_bfloat16 g_xh[NROW * D];   // layernormed pair, bf16 hi
__device__ __align__(16) __nv_bfloat16 g_xl[NROW * D];   // bf16 lo
__device__ __align__(16) __half g_qh [NROW * D];  // [i][h][j][d], fp16, pre-scaled
__device__ __align__(16) __half g_kh [NROW * D];  // [i][h][j][d], fp16 hi
__device__ __align__(16) __half g_kl [NROW * D];  // fp16 lo
__device__ __align__(16) __half g_vth[NROW * D];  // [i][h][d][j] (transposed), fp16
__device__ __align__(16) float g_g   [NROW * D];  // row layout, sigmoid applied
__device__ __align__(16) uint32_t g_ohp[NROW * 64]; // gated attn out, bf16x2 hi
__device__ __align__(16) uint32_t g_olp[NROW * 64]; // bf16x2 lo
__device__ float g_bias[L * H * L];  // [i][h][j]  (pre-scaled by LOG2E)
__device__ __align__(16) __nv_bfloat16 g_wh[5 * D * D];  // pre-split: Wq,Wk,Wv,Wg,Wo
__device__ __align__(16) __nv_bfloat16 g_wl[5 * D * D];

// single extern shared symbol for all kernels
extern __shared__ char smx[];

// ---------------- helpers ----------------
__device__ __forceinline__ float ex2f(float x) {
    float r; asm("ex2.approx.f32 %0, %1;" : "=f"(r) : "f"(x)); return r;
}
__device__ __forceinline__ uint32_t smem_u32(const void* p) {
    return (uint32_t)__cvta_generic_to_shared(p);
}
__device__ __forceinline__ void ldsm4(uint32_t* r, uint32_t addr) {
    asm volatile("ldmatrix.sync.aligned.m8n8.x4.shared.b16 {%0,%1,%2,%3}, [%4];"
                 : "=r"(r[0]), "=r"(r[1]), "=r"(r[2]), "=r"(r[3]) : "r"(addr));
}
__device__ __forceinline__ void mma16816(float* c, const uint32_t* a, const uint32_t* b) {
    asm volatile("mma.sync.aligned.m16n8k16.row.col.f32.bf16.bf16.f32 "
                 "{%0,%1,%2,%3}, {%4,%5,%6,%7}, {%8,%9}, {%0,%1,%2,%3};"
                 : "+f"(c[0]), "+f"(c[1]), "+f"(c[2]), "+f"(c[3])
                 : "r"(a[0]), "r"(a[1]), "r"(a[2]), "r"(a[3]), "r"(b[0]), "r"(b[1]));
}
__device__ __forceinline__ void mma16816h(float* c, const uint32_t* a, const uint32_t* b) {
    asm volatile("mma.sync.aligned.m16n8k16.row.col.f32.f16.f16.f32 "
                 "{%0,%1,%2,%3}, {%4,%5,%6,%7}, {%8,%9}, {%0,%1,%2,%3};"
                 : "+f"(c[0]), "+f"(c[1]), "+f"(c[2]), "+f"(c[3])
                 : "r"(a[0]), "r"(a[1]), "r"(a[2]), "r"(a[3]), "r"(b[0]), "r"(b[1]));
}
// split fp32 pair -> (hi bf16x2, lo bf16x2) packed as uint32
__device__ __forceinline__ void split2(float x0, float x1, uint32_t& hi, uint32_t& lo) {
    __nv_bfloat16 h0 = __float2bfloat16(x0);
    __nv_bfloat16 h1 = __float2bfloat16(x1);
    __nv_bfloat16 l0 = __float2bfloat16(x0 - __bfloat162float(h0));
    __nv_bfloat16 l1 = __float2bfloat16(x1 - __bfloat162float(h1));
    __nv_bfloat162 hp = {h0, h1}, lp = {l0, l1};
    hi = *(uint32_t*)&hp; lo = *(uint32_t*)&lp;
}
__device__ __forceinline__ uint32_t pkh2(float a, float b) {
    __half2 h = __floats2half2_rn(a, b);
    return *(uint32_t*)&h;
}

// shared tile geometry for GEMM kernels: 128 x 136 bf16 (272B stride)
#define TROW   272
#define TBYTES (128 * TROW)      // 34816
#define XH_OFF 0
#define XL_OFF TBYTES
#define WH_OFF (2 * TBYTES)
#define WL_OFF (3 * TBYTES)
#define GEMM_SMEM (4 * TBYTES)   // 139264

// ================= kernel 0: pre-split weights =================
__global__ void k_wsplit(const float* __restrict__ Wq, const float* __restrict__ Wk,
                         const float* __restrict__ Wv, const float* __restrict__ Wg,
                         const float* __restrict__ Wo) {
    int idx = blockIdx.x * blockDim.x + threadIdx.x;   // over 5*8192 float2
    if (idx >= 5 * 8192) return;
    int m = idx / 8192, off = idx % 8192;
    const float* W = (m == 0) ? Wq : (m == 1) ? Wk : (m == 2) ? Wv : (m == 3) ? Wg : Wo;
    float2 v = *(const float2*)&W[off * 2];
    uint32_t hi, lo;
    split2(v.x, v.y, hi, lo);
    *(uint32_t*)&g_wh[m * 16384 + off * 2] = hi;
    *(uint32_t*)&g_wl[m * 16384 + off * 2] = lo;
}

// ================= kernel 1: layernorm + bias projection =================
__global__ void k_ln_bias(const float* __restrict__ pair,
                          const float* __restrict__ nw,
                          const float* __restrict__ nb,
                          const float* __restrict__ Wb) {
    int row = blockIdx.x;
    int t   = threadIdx.x;
    int w   = t >> 5, lane = t & 31;

    float p = pair[(size_t)row * D + t];

    __shared__ float px[D];
    __shared__ float rs[4], rs2[4];
    px[t] = p;

    float s = p, s2 = p * p;
    #pragma unroll
    for (int o = 16; o > 0; o >>= 1) {
        s  += __shfl_xor_sync(0xffffffffu, s,  o);
        s2 += __shfl_xor_sync(0xffffffffu, s2, o);
    }
    if (lane == 0) { rs[w] = s; rs2[w] = s2; }
    __syncthreads();

    float mean = (rs[0] + rs[1] + rs[2] + rs[3]) * (1.0f / 128.0f);
    float var  = (rs2[0] + rs2[1] + rs2[2] + rs2[3]) * (1.0f / 128.0f) - mean * mean;
    float inv  = rsqrtf(var + 1e-5f);
    float xv = (p - mean) * inv * nw[t] + nb[t];
    __nv_bfloat16 xh = __float2bfloat16(xv);
    g_xh[(size_t)row * D + t] = xh;
    g_xl[(size_t)row * D + t] = __float2bfloat16(xv - __bfloat162float(xh));

    const float* wb = Wb + w * D;
    float bv = px[lane]      * wb[lane]
             + px[lane + 32] * wb[lane + 32]
             + px[lane + 64] * wb[lane + 64]
             + px[lane + 96] * wb[lane + 96];
    #pragma unroll
    for (int o = 16; o > 0; o >>= 1)
        bv += __shfl_xor_sync(0xffffffffu, bv, o);
    if (lane == 0) {
        int i = row / L, j = row % L;
        g_bias[(i * H + w) * L + j] = bv * LOG2E;
    }
}

// ---------- pure-copy staging: bf16 row-major [128x128] -> TROW-strided smem ----------
__device__ __forceinline__ void stage_copy(const __nv_bfloat16* __restrict__ src,
                                           char* sm, int off, int t) {
    const uint4* s = (const uint4*)src;
    for (int idx = t; idx < 128 * 16; idx += 256) {
        int r = idx >> 4, c = idx & 15;
        *(uint4*)(sm + off + r * TROW + c * 16) = s[idx];
    }
}

// ---------- 3-term bf16-split 128x128x128 GEMM into registers (64x32 warp tile) ----------
__device__ __forceinline__ void gemm_tile(uint32_t sb, float (&acc)[4][4][4],
                                          int lane, int wm, int wn) {
    int gq = lane >> 3, r8 = lane & 7;
    uint32_t a_off = (uint32_t)(wm * 64 + (gq & 1) * 8 + r8) * TROW + (uint32_t)(gq >> 1) * 16;
    uint32_t b_off = (uint32_t)(wn * 32 + (gq >> 1) * 8 + r8) * TROW + (uint32_t)(gq & 1) * 16;

    #pragma unroll
    for (int term = 0; term < 3; term++) {
        uint32_t abase = sb + ((term == 2) ? XL_OFF : XH_OFF) + a_off;
        uint32_t bbase = sb + ((term == 1) ? WL_OFF : WH_OFF) + b_off;
        #pragma unroll
        for (int ks = 0; ks < 8; ks++) {
            uint32_t kb = ks * 32;
            uint32_t a[4][4], b[2][4];
            #pragma unroll
            for (int mt = 0; mt < 4; mt++)
                ldsm4(a[mt], abase + mt * (16 * TROW) + kb);
            #pragma unroll
            for (int nb = 0; nb < 2; nb++)
                ldsm4(b[nb], bbase + nb * (16 * TROW) + kb);
            #pragma unroll
            for (int mt = 0; mt < 4; mt++) {
                mma16816(acc[mt][0], a[mt], &b[0][0]);
                mma16816(acc[mt][1], a[mt], &b[0][2]);
                mma16816(acc[mt][2], a[mt], &b[1][0]);
                mma16816(acc[mt][3], a[mt], &b[1][2]);
            }
        }
    }
}

// ================= kernel 2: Q/K/V/G projections via mma.sync =================
__global__ __launch_bounds__(256) void k_proj(const float* __restrict__ bg) {
    char* sm = smx;
    uint32_t sb = smem_u32(sm);
    int t = threadIdx.x, w = t >> 5, lane = t & 31;
    int wm = w & 1, wn = w >> 1;
    int base = blockIdx.x * 128;

    stage_copy(g_xh + (size_t)base * 128, sm, XH_OFF, t);
    stage_copy(g_xl + (size_t)base * 128, sm, XL_OFF, t);

    for (int m = 0; m < 4; m++) {
        __syncthreads();
        stage_copy(g_wh + m * 16384, sm, WH_OFF, t);
        stage_copy(g_wl + m * 16384, sm, WL_OFF, t);
        __syncthreads();

        float acc[4][4][4];
        #pragma unroll
        for (int mt = 0; mt < 4; mt++)
            #pragma unroll
            for (int nt = 0; nt < 4; nt++)
                #pragma unroll
                for (int k = 0; k < 4; k++) acc[mt][nt][k] = 0.0f;

        gemm_tile(sb, acc, lane, wm, wn);

        #pragma unroll
        for (int mt = 0; mt < 4; mt++) {
            #pragma unroll
            for (int nt = 0; nt < 4; nt++) {
                int d = nt * 8 + (lane & 3) * 2;   // head dim within head wn
                #pragma unroll
                for (int half = 0; half < 2; half++) {
                    int R = base + wm * 64 + mt * 16 + (lane >> 2) + half * 8;
                    float v0 = acc[mt][nt][half * 2];
                    float v1 = acc[mt][nt][half * 2 + 1];
                    int i = R / L, j = R % L;
                    size_t hb = (((size_t)i * H + wn) * L + j) * DH + d;
                    if (m == 0) {
                        *(uint32_t*)&g_qh[hb] = pkh2(v0 * (SCALE * LOG2E), v1 * (SCALE * LOG2E));
                    } else if (m == 1) {
                        __half h0 = __float2half_rn(v0), h1 = __float2half_rn(v1);
                        __half l0 = __float2half_rn(v0 - __half2float(h0));
                        __half l1 = __float2half_rn(v1 - __half2float(h1));
                        *(uint32_t*)&g_kh[hb] = (uint32_t)__half_as_ushort(h0)
                                              | ((uint32_t)__half_as_ushort(h1) << 16);
                        *(uint32_t*)&g_kl[hb] = (uint32_t)__half_as_ushort(l0)
                                              | ((uint32_t)__half_as_ushort(l1) << 16);
                    } else if (m == 2) {
                        size_t vb = (((size_t)i * H + wn) * DH + d) * L + j;
                        g_vth[vb]     = __float2half_rn(v0);
                        g_vth[vb + L] = __float2half_rn(v1);
                    } else {
                        int col = wn * 32 + d;
                        float a0 = v0 + bg[col], a1 = v1 + bg[col + 1];
                        *(float2*)&g_g[(size_t)R * D + col] =
                            make_float2(1.0f / (1.0f + __expf(-a0)),
                                        1.0f / (1.0f + __expf(-a1)));
                    }
                }
            }
        }
    }
}

// ================= kernel 3: tensor-core attention per (i,h), 2 CTAs/SM =================
// smem: Q fp16 [336+pad x 32] stride 80B; K hi/lo [320 x 32] stride 80B;
//       V^T fp16 [32 x 320] stride 656B; bias [320] fp32
#define AQH 0
#define AKH 30720
#define AKL 56320
#define AVH 81920
#define ABI 102912
#define ATTN_SMEM 104192

__global__ __launch_bounds__(256, 2) void k_attn() {
    char* sm = smx;
    uint32_t sb = smem_u32(sm);

    int blk = blockIdx.x;
    int i = blk >> 2, h = blk & 3;
    int t = threadIdx.x, w = t >> 5, lane = t & 31;

    size_t hb = ((size_t)i * H + h) * L * DH;
    const uint4* Qg = (const uint4*)(g_qh + hb);
    const uint4* Kh = (const uint4*)(g_kh + hb);
    const uint4* Kl = (const uint4*)(g_kl + hb);
    const uint4* Vt = (const uint4*)(g_vth + hb);

    // pure-copy staging (Q/K rows: 4 uint4 per 32-d row; V^T rows: 40 uint4 per 320-j row)
    for (int idx = t; idx < 320 * 4; idx += 256) {
        int j = idx >> 2, c = idx & 3;
        *(uint4*)(sm + AQH + j * 80 + c * 16) = Qg[idx];
        *(uint4*)(sm + AKH + j * 80 + c * 16) = Kh[idx];
        *(uint4*)(sm + AKL + j * 80 + c * 16) = Kl[idx];
    }
    for (int idx = t; idx < 32 * 40; idx += 256) {
        int d = idx / 40, c = idx % 40;
        *(uint4*)(sm + AVH + d * 656 + c * 16) = Vt[idx];
    }
    // zero-pad Q rows 320..335
    uint4 z = make_uint4(0, 0, 0, 0);
    for (int idx = t; idx < 16 * 4; idx += 256) {
        int j = 320 + (idx >> 2), c = idx & 3;
        *(uint4*)(sm + AQH + j * 80 + c * 16) = z;
    }
    for (int idx = t; idx < L; idx += 256)
        *(float*)(sm + ABI + idx * 4) = g_bias[(i * H + h) * L + idx];
    __syncthreads();

    if (w == 7) return;   // rows 336+ unused

    int gq = lane >> 3, r8 = lane & 7;
    uint32_t qbase = sb + AQH + (uint32_t)(48 * w + (gq & 1) * 8 + r8) * 80 + (uint32_t)(gq >> 1) * 16;
    uint32_t kbase = sb + AKH + (uint32_t)((gq >> 1) * 8 + r8) * 80 + (uint32_t)(gq & 1) * 16;
    uint32_t vbase = sb + AVH + (uint32_t)((gq >> 1) * 8 + r8) * 656 + (uint32_t)(gq & 1) * 16;
    const float* Bsp = (const float*)(sm + ABI);

    float O[3][4][4];
    float ds[3][2];
    #pragma unroll
    for (int mt = 0; mt < 3; mt++) {
        ds[mt][0] = 0.0f; ds[mt][1] = 0.0f;
        #pragma unroll
        for (int nt = 0; nt < 4; nt++)
            #pragma unroll
            for (int k = 0; k < 4; k++) O[mt][nt][k] = 0.0f;
    }

    #pragma unroll 1
    for (int nb = 0; nb < 10; nb++) {   // 32 keys per chunk
        float S[3][4][4];
        #pragma unroll
        for (int mt = 0; mt < 3; mt++)
            #pragma unroll
            for (int nt = 0; nt < 4; nt++)
                #pragma unroll
                for (int k = 0; k < 4; k++) S[mt][nt][k] = 0.0f;

        #pragma unroll
        for (int ks = 0; ks < 2; ks++) {
            uint32_t Ah[3][4], Bh[2][4], Bl[2][4];
            #pragma unroll
            for (int mt = 0; mt < 3; mt++)
                ldsm4(Ah[mt], qbase + mt * 1280 + ks * 32);
            #pragma unroll
            for (int nt = 0; nt < 2; nt++) {
                uint32_t ko = (uint32_t)(nb * 32 + nt * 16) * 80 + ks * 32;
                ldsm4(Bh[nt], kbase + ko);
                ldsm4(Bl[nt], kbase + (AKL - AKH) + ko);
            }
            #pragma unroll
            for (int mt = 0; mt < 3; mt++)
                #pragma unroll
                for (int nt = 0; nt < 2; nt++) {
                    mma16816h(S[mt][2 * nt],     Ah[mt], &Bh[nt][0]);
                    mma16816h(S[mt][2 * nt + 1], Ah[mt], &Bh[nt][2]);
                    mma16816h(S[mt][2 * nt],     Ah[mt], &Bl[nt][0]);
                    mma16816h(S[mt][2 * nt + 1], Ah[mt], &Bl[nt][2]);
                }
        }

        #pragma unroll
        for (int nt = 0; nt < 2; nt++) {
            int c0 = nb * 32 + nt * 16 + 2 * (lane & 3);
            float b00 = Bsp[c0], b01 = Bsp[c0 + 1];
            float b10 = Bsp[c0 + 8], b11 = Bsp[c0 + 9];

            uint32_t PAh[3][4];
            #pragma unroll
            for (int mt = 0; mt < 3; mt++) {
                float e00 = ex2f(S[mt][2 * nt][0] + b00);
                float e01 = ex2f(S[mt][2 * nt][1] + b01);
                float e10 = ex2f(S[mt][2 * nt][2] + b00);
                float e11 = ex2f(S[mt][2 * nt][3] + b01);
                float f00 = ex2f(S[mt][2 * nt + 1][0] + b10);
                float f01 = ex2f(S[mt][2 * nt + 1][1] + b11);
                float f10 = ex2f(S[mt][2 * nt + 1][2] + b10);
                float f11 = ex2f(S[mt][2 * nt + 1][3] + b11);
                ds[mt][0] += (e00 + e01) + (f00 + f01);
                ds[mt][1] += (e10 + e11) + (f10 + f11);
                PAh[mt][0] = pkh2(e00, e01);
                PAh[mt][1] = pkh2(e10, e11);
                PAh[mt][2] = pkh2(f00, f01);
                PAh[mt][3] = pkh2(f10, f11);
            }

            uint32_t Vh2[2][4];
            #pragma unroll
            for (int dn = 0; dn < 2; dn++) {
                uint32_t vo = (uint32_t)dn * (16 * 656) + (uint32_t)(nb * 32 + nt * 16) * 2;
                ldsm4(Vh2[dn], vbase + vo);
            }
            #pragma unroll
            for (int mt = 0; mt < 3; mt++)
                #pragma unroll
                for (int dn = 0; dn < 2; dn++) {
                    mma16816h(O[mt][2 * dn],     PAh[mt], &Vh2[dn][0]);
                    mma16816h(O[mt][2 * dn + 1], PAh[mt], &Vh2[dn][2]);
                }
        }
    }

    #pragma unroll
    for (int mt = 0; mt < 3; mt++)
        #pragma unroll
        for (int rr = 0; rr < 2; rr++) {
            ds[mt][rr] += __shfl_xor_sync(0xffffffffu, ds[mt][rr], 1);
            ds[mt][rr] += __shfl_xor_sync(0xffffffffu, ds[mt][rr], 2);
        }

    // normalize, gate, split to bf16 hi/lo, store
    #pragma unroll
    for (int mt = 0; mt < 3; mt++) {
        float inv0 = __fdividef(1.0f, ds[mt][0]);
        float inv1 = __fdividef(1.0f, ds[mt][1]);
        #pragma unroll
        for (int half = 0; half < 2; half++) {
            int r = 48 * w + mt * 16 + (lane >> 2) + half * 8;
            if (r < L) {
                float inv = half ? inv1 : inv0;
                size_t R = ((size_t)i * L + r) * D + h * DH;
                #pragma unroll
                for (int nt = 0; nt < 4; nt++) {
                    int d = nt * 8 + 2 * (lane & 3);
                    float2 gv = *(const float2*)&g_g[R + d];
                    float o0 = O[mt][nt][half * 2] * inv * gv.x;
                    float o1 = O[mt][nt][half * 2 + 1] * inv * gv.y;
                    uint32_t hi, lo;
                    split2(o0, o1, hi, lo);
                    g_ohp[(R + d) >> 1] = hi;
                    g_olp[(R + d) >> 1] = lo;
                }
            }
        }
    }
}

// ================= kernel 4: output projection + residual via mma.sync =================
__global__ __launch_bounds__(256) void k_out(const float* __restrict__ bo,
                                             const float* __restrict__ pair,
                                             float* __restrict__ out) {
    char* sm = smx;
    uint32_t sb = smem_u32(sm);
    int t = threadIdx.x, w = t >> 5, lane = t & 31;
    int wm = w & 1, wn = w >> 1;
    int base = blockIdx.x * 128;

    stage_copy((const __nv_bfloat16*)g_ohp + (size_t)base * 128, sm, XH_OFF, t);
    stage_copy((const __nv_bfloat16*)g_olp + (size_t)base * 128, sm, XL_OFF, t);
    stage_copy(g_wh + 4 * 16384, sm, WH_OFF, t);
    stage_copy(g_wl + 4 * 16384, sm, WL_OFF, t);
    __syncthreads();

    float acc[4][4][4];
    #pragma unroll
    for (int mt = 0; mt < 4; mt++)
        #pragma unroll
        for (int nt = 0; nt < 4; nt++)
            #pragma unroll
            for (int k = 0; k < 4; k++) acc[mt][nt][k] = 0.0f;

    gemm_tile(sb, acc, lane, wm, wn);

    #pragma unroll
    for (int mt = 0; mt < 4; mt++) {
        #pragma unroll
        for (int nt = 0; nt < 4; nt++) {
            int col = wn * 32 + nt * 8 + (lane & 3) * 2;
            float2 bov = *(const float2*)&bo[col];
            #pragma unroll
            for (int half = 0; half < 2; half++) {
                size_t R = (size_t)base + wm * 64 + mt * 16 + (lane >> 2) + half * 8;
                float2 pv = *(const float2*)&pair[R * D + col];
                *(float2*)&out[R * D + col] =
                    make_float2(pv.x + acc[mt][nt][half * 2]     + bov.x,
                                pv.y + acc[mt][nt][half * 2 + 1] + bov.y);
            }
        }
    }
}

// ================= launch =================
extern "C" void kernel_launch(void* const* d_in, const int* in_sizes, int n_in,
                              void* d_out, int out_size) {
    const float* pair  = (const float*)d_in[0];
    const float* nw    = (const float*)d_in[1];
    const float* nb    = (const float*)d_in[2];
    const float* Wq    = (const float*)d_in[3];
    const float* Wk    = (const float*)d_in[4];
    const float* Wv    = (const float*)d_in[5];
    const float* Wg    = (const float*)d_in[6];
    const float* bg    = (const float*)d_in[7];
    const float* Wo    = (const float*)d_in[8];
    const float* bo    = (const float*)d_in[9];
    const float* Wb    = (const float*)d_in[10];
    float* out = (float*)d_out;

    static bool attr_set = false;
    if (!attr_set) {
        cudaFuncSetAttribute(k_attn, cudaFuncAttributeMaxDynamicSharedMemorySize, ATTN_SMEM);
        cudaFuncSetAttribute(k_proj, cudaFuncAttributeMaxDynamicSharedMemorySize, GEMM_SMEM);
        cudaFuncSetAttribute(k_out,  cudaFuncAttributeMaxDynamicSharedMemorySize, GEMM_SMEM);
        attr_set = true;
    }

    k_wsplit <<<160, 256>>>(Wq, Wk, Wv, Wg, Wo);
    k_ln_bias<<<NROW, 128>>>(pair, nw, nb, Wb);
    k_proj   <<<NROW / 128, 256, GEMM_SMEM>>>(bg);
    k_attn   <<<L * H, 256, ATTN_SMEM>>>();
    k_out    <<<NROW / 128, 256, GEMM_SMEM>>>(bo, pair, out);
}